// round 1
// baseline (speedup 1.0000x reference)
#include <cuda_runtime.h>

#define DB 4
#define DC 256
#define DN 4096
#define DD 16

// Scratch (allocation-free rule: __device__ globals)
__device__ float g_q[DB*DN*DD];   // [b][n][d]
__device__ float g_k[DB*DN*DD];   // [b][m][d]
__device__ float g_v[DB*DN*DC];   // [b][m][c]

// ---------------------------------------------------------------------------
// Kernel 1: q/k projection.  q[b,n,o] = sum_c wq[o,c] x[b,c,n] + bq[o]
// Grid (N/64, B), 256 threads. Tile x [64c x 64n] through smem.
// ---------------------------------------------------------------------------
__global__ __launch_bounds__(256) void qk_proj_kernel(
    const float* __restrict__ x,
    const float* __restrict__ wq, const float* __restrict__ bq,
    const float* __restrict__ wk, const float* __restrict__ bk)
{
    __shared__ float xt[64][64];
    __shared__ float wqs[16][64];
    __shared__ float wks[16][64];
    const int b = blockIdx.y, n0 = blockIdx.x * 64, tid = threadIdx.x;
    const int n = tid & 63, og = tid >> 6;           // og in 0..3 -> 4 outputs each
    float aq[4] = {0.f,0.f,0.f,0.f};
    float ak[4] = {0.f,0.f,0.f,0.f};

    for (int c0 = 0; c0 < DC; c0 += 64) {
        __syncthreads();
        {
            const int j4 = (tid & 15) * 4, rb = tid >> 4;
            #pragma unroll
            for (int i = 0; i < 4; ++i) {
                int r = rb + i * 16;
                *(float4*)&xt[r][j4] =
                    *(const float4*)(x + ((size_t)b*DC + c0 + r)*DN + n0 + j4);
            }
            *(float4*)&wqs[rb][j4] = *(const float4*)(wq + rb*DC + c0 + j4);
            *(float4*)&wks[rb][j4] = *(const float4*)(wk + rb*DC + c0 + j4);
        }
        __syncthreads();
        #pragma unroll 16
        for (int cc = 0; cc < 64; ++cc) {
            float xv = xt[cc][n];
            #pragma unroll
            for (int oo = 0; oo < 4; ++oo) {
                aq[oo] = fmaf(wqs[og*4+oo][cc], xv, aq[oo]);
                ak[oo] = fmaf(wks[og*4+oo][cc], xv, ak[oo]);
            }
        }
    }
    float4 q4, k4;
    q4.x = aq[0] + bq[og*4+0]; q4.y = aq[1] + bq[og*4+1];
    q4.z = aq[2] + bq[og*4+2]; q4.w = aq[3] + bq[og*4+3];
    k4.x = ak[0] + bk[og*4+0]; k4.y = ak[1] + bk[og*4+1];
    k4.z = ak[2] + bk[og*4+2]; k4.w = ak[3] + bk[og*4+3];
    const int base = (b*DN + n0 + n)*DD + og*4;
    *(float4*)&g_q[base] = q4;
    *(float4*)&g_k[base] = k4;
}

// ---------------------------------------------------------------------------
// Kernel 2: V projection GEMM. v[b,n,c] = sum_c' wv[c,c'] x[b,c',n] + bv[c]
// Grid (N/64, C/64, B), 256 threads, 64x64 tile, 4x4 microtile/thread.
// Output layout [b][m][c] (channel-contiguous rows) for coalesced P*V.
// ---------------------------------------------------------------------------
__global__ __launch_bounds__(256) void v_proj_kernel(
    const float* __restrict__ x,
    const float* __restrict__ wv, const float* __restrict__ bv)
{
    __shared__ float xs[64][64];    // [c'][n]
    __shared__ float ws[64][68];    // [c'][c]  (wv chunk, transposed, padded)
    const int b = blockIdx.z, c0 = blockIdx.y * 64, n0 = blockIdx.x * 64;
    const int tid = threadIdx.x;
    const int tn = tid & 15, tc = tid >> 4;          // 16 n-groups x 16 c-groups
    float acc[4][4];
    #pragma unroll
    for (int i = 0; i < 4; ++i)
        #pragma unroll
        for (int j = 0; j < 4; ++j) acc[i][j] = 0.f;

    for (int k0 = 0; k0 < DC; k0 += 64) {
        __syncthreads();
        {
            const int j4 = (tid & 15) * 4, rb = tid >> 4;
            #pragma unroll
            for (int i = 0; i < 4; ++i) {
                int r = rb + i * 16;
                *(float4*)&xs[r][j4] =
                    *(const float4*)(x + ((size_t)b*DC + k0 + r)*DN + n0 + j4);
                float4 w = *(const float4*)(wv + (size_t)(c0 + r)*DC + k0 + j4);
                ws[j4+0][r] = w.x; ws[j4+1][r] = w.y;
                ws[j4+2][r] = w.z; ws[j4+3][r] = w.w;
            }
        }
        __syncthreads();
        #pragma unroll 8
        for (int kk = 0; kk < 64; ++kk) {
            float4 a = *(float4*)&xs[kk][tn*4];
            float4 w = *(float4*)&ws[kk][tc*4];
            acc[0][0]=fmaf(w.x,a.x,acc[0][0]); acc[0][1]=fmaf(w.x,a.y,acc[0][1]);
            acc[0][2]=fmaf(w.x,a.z,acc[0][2]); acc[0][3]=fmaf(w.x,a.w,acc[0][3]);
            acc[1][0]=fmaf(w.y,a.x,acc[1][0]); acc[1][1]=fmaf(w.y,a.y,acc[1][1]);
            acc[1][2]=fmaf(w.y,a.z,acc[1][2]); acc[1][3]=fmaf(w.y,a.w,acc[1][3]);
            acc[2][0]=fmaf(w.z,a.x,acc[2][0]); acc[2][1]=fmaf(w.z,a.y,acc[2][1]);
            acc[2][2]=fmaf(w.z,a.z,acc[2][2]); acc[2][3]=fmaf(w.z,a.w,acc[2][3]);
            acc[3][0]=fmaf(w.w,a.x,acc[3][0]); acc[3][1]=fmaf(w.w,a.y,acc[3][1]);
            acc[3][2]=fmaf(w.w,a.z,acc[3][2]); acc[3][3]=fmaf(w.w,a.w,acc[3][3]);
        }
    }
    float4 bvv = *(const float4*)(bv + c0 + tc*4);
    #pragma unroll
    for (int ni = 0; ni < 4; ++ni) {
        float4 o;
        o.x = acc[0][ni] + bvv.x; o.y = acc[1][ni] + bvv.y;
        o.z = acc[2][ni] + bvv.z; o.w = acc[3][ni] + bvv.w;
        *(float4*)&g_v[(b*DN + n0 + tn*4 + ni)*DC + c0 + tc*4] = o;
    }
}

// ---------------------------------------------------------------------------
// Kernel 3: flash attention + epilogue (gamma*out + x).
// Grid (N/64, B), 256 threads. 64-query tile, 64-key tiles, online softmax.
// Thread (rg=warp 0..7, cg=lane 0..31) owns 8 rows x 8 channels (64 fp32 acc).
// ---------------------------------------------------------------------------
__global__ __launch_bounds__(256, 2) void attn_kernel(
    const float* __restrict__ x, float* __restrict__ y,
    const float* __restrict__ gamma)
{
    extern __shared__ float sm[];
    float* qs = sm;              // 64*16  = 1024 floats
    float* ks = sm + 1024;       // 64*16  = 1024 floats
    float* ps = sm + 2048;       // 64*65  = 4160 floats (padded rows)
    __shared__ float srm[64], srl[64], sfac[64];

    const int b = blockIdx.y, n0 = blockIdx.x * 64, tid = threadIdx.x;
    const int rg = tid >> 5, cg = tid & 31;
    const int sr = tid >> 2, smq = tid & 3;   // s-phase: (row, quarter)

    float acc[8][8];
    #pragma unroll
    for (int i = 0; i < 8; ++i)
        #pragma unroll
        for (int j = 0; j < 8; ++j) acc[i][j] = 0.f;

    ((float4*)qs)[tid] = ((const float4*)(g_q + (b*DN + n0)*DD))[tid];
    if (tid < 64) { srm[tid] = -1e30f; srl[tid] = 0.f; }

    for (int m0 = 0; m0 < DN; m0 += 64) {
        __syncthreads();   // prev tile done with ks/ps
        ((float4*)ks)[tid] = ((const float4*)(g_k + (b*DN + m0)*DD))[tid];
        __syncthreads();

        // scores: each thread does 16 dots of dim 16 for row sr
        float qr[16];
        #pragma unroll
        for (int i = 0; i < 4; ++i) {
            float4 t = ((float4*)(qs + sr*16))[i];
            qr[i*4+0]=t.x; qr[i*4+1]=t.y; qr[i*4+2]=t.z; qr[i*4+3]=t.w;
        }
        #pragma unroll
        for (int j = 0; j < 16; ++j) {
            int m = smq*16 + j;
            const float* kr = ks + m*16;
            float s = 0.f;
            #pragma unroll
            for (int d = 0; d < 16; ++d) s = fmaf(qr[d], kr[d], s);
            ps[sr*65 + m] = s;
        }
        __syncthreads();

        // online softmax stats: one thread per row
        if (tid < 64) {
            float tmax = -1e30f;
            #pragma unroll 8
            for (int m = 0; m < 64; ++m) tmax = fmaxf(tmax, ps[tid*65+m]);
            float om = srm[tid];
            float nm = fmaxf(om, tmax);
            float f  = __expf(om - nm);
            float s  = 0.f;
            #pragma unroll 8
            for (int m = 0; m < 64; ++m) {
                float p = __expf(ps[tid*65+m] - nm);
                ps[tid*65+m] = p;
                s += p;
            }
            srm[tid]  = nm;
            srl[tid]  = srl[tid]*f + s;
            sfac[tid] = f;
        }
        __syncthreads();

        #pragma unroll
        for (int i = 0; i < 8; ++i) {
            float f = sfac[rg*8+i];
            #pragma unroll
            for (int j = 0; j < 8; ++j) acc[i][j] *= f;
        }

        // P*V accumulate: v rows are channel-contiguous; warp reads full row
        const float* vb = g_v + (b*DN + m0)*DC + cg*8;
        #pragma unroll 2
        for (int m = 0; m < 64; ++m) {
            float4 v0 = *(const float4*)(vb + m*DC);
            float4 v1 = *(const float4*)(vb + m*DC + 4);
            #pragma unroll
            for (int i = 0; i < 8; ++i) {
                float p = ps[(rg*8+i)*65 + m];
                acc[i][0]=fmaf(p,v0.x,acc[i][0]); acc[i][1]=fmaf(p,v0.y,acc[i][1]);
                acc[i][2]=fmaf(p,v0.z,acc[i][2]); acc[i][3]=fmaf(p,v0.w,acc[i][3]);
                acc[i][4]=fmaf(p,v1.x,acc[i][4]); acc[i][5]=fmaf(p,v1.y,acc[i][5]);
                acc[i][6]=fmaf(p,v1.z,acc[i][6]); acc[i][7]=fmaf(p,v1.w,acc[i][7]);
            }
        }
    }
    __syncthreads();

    float inv[8];
    #pragma unroll
    for (int i = 0; i < 8; ++i) inv[i] = 1.0f / srl[rg*8+i];
    const float g = gamma[0];
    float* outs = sm;  // reuse all smem: [128][68] per half (c-major staging)

    #pragma unroll 1
    for (int half = 0; half < 2; ++half) {
        __syncthreads();
        if ((cg >> 4) == half) {
            int crow = (cg & 15) * 8;   // local channel base within half
            #pragma unroll
            for (int j = 0; j < 8; ++j) {
                float4 o0, o1;
                o0.x=acc[0][j]*inv[0]; o0.y=acc[1][j]*inv[1];
                o0.z=acc[2][j]*inv[2]; o0.w=acc[3][j]*inv[3];
                o1.x=acc[4][j]*inv[4]; o1.y=acc[5][j]*inv[5];
                o1.z=acc[6][j]*inv[6]; o1.w=acc[7][j]*inv[7];
                *(float4*)&outs[(crow+j)*68 + rg*8]     = o0;
                *(float4*)&outs[(crow+j)*68 + rg*8 + 4] = o1;
            }
        }
        __syncthreads();
        {
            const int j = (tid & 15) * 4, cb = tid >> 4;
            #pragma unroll
            for (int i = 0; i < 8; ++i) {
                int cl = cb + i*16;
                int c  = half*128 + cl;
                float4 xv = *(const float4*)(x + ((size_t)b*DC + c)*DN + n0 + j);
                float4 ov = *(const float4*)&outs[cl*68 + j];
                float4 r;
                r.x = fmaf(g, ov.x, xv.x); r.y = fmaf(g, ov.y, xv.y);
                r.z = fmaf(g, ov.z, xv.z); r.w = fmaf(g, ov.w, xv.w);
                *(float4*)(y + ((size_t)b*DC + c)*DN + n0 + j) = r;
            }
        }
    }
}

// ---------------------------------------------------------------------------
extern "C" void kernel_launch(void* const* d_in, const int* in_sizes, int n_in,
                              void* d_out, int out_size)
{
    const float* x     = (const float*)d_in[0];
    const float* wq    = (const float*)d_in[1];
    const float* bq    = (const float*)d_in[2];
    const float* wk    = (const float*)d_in[3];
    const float* bk    = (const float*)d_in[4];
    const float* wv    = (const float*)d_in[5];
    const float* bv    = (const float*)d_in[6];
    const float* gamma = (const float*)d_in[7];
    float* y = (float*)d_out;

    qk_proj_kernel<<<dim3(DN/64, DB), 256>>>(x, wq, bq, wk, bk);
    v_proj_kernel<<<dim3(DN/64, DC/64, DB), 256>>>(x, wv, bv);
    // dynamic smem: max(loop phase 6208 floats, staging 128*68=8704 floats)
    attn_kernel<<<dim3(DN/64, DB), 256, 8704*sizeof(float)>>>(x, y, gamma);
}

// round 2
// speedup vs baseline: 3.7031x; 3.7031x over previous
#include <cuda_runtime.h>
#include <cstdint>

#define DB 4
#define DC 256
#define DN 4096
#define DD 16

#define QSP 20
#define KSP 20
#define PSP 68
#define VSP 264
#define OSP 68

// Scratch (allocation-free rule: __device__ globals)
__device__ float g_q[DB*DN*DD];   // [b][n][d]
__device__ float g_k[DB*DN*DD];   // [b][m][d]
__device__ float g_v[DB*DN*DC];   // [b][m][c]

// ---------------------------------------------------------------------------
// tf32 mma m16n8k8 (fp32 accum)
// ---------------------------------------------------------------------------
__device__ __forceinline__ void mma_tf32(float& d0, float& d1, float& d2, float& d3,
    uint32_t a0, uint32_t a1, uint32_t a2, uint32_t a3, uint32_t b0, uint32_t b1)
{
    asm volatile(
        "mma.sync.aligned.m16n8k8.row.col.f32.tf32.tf32.f32 "
        "{%0,%1,%2,%3}, {%4,%5,%6,%7}, {%8,%9}, {%0,%1,%2,%3};\n"
        : "+f"(d0), "+f"(d1), "+f"(d2), "+f"(d3)
        : "r"(a0), "r"(a1), "r"(a2), "r"(a3), "r"(b0), "r"(b1));
}
__device__ __forceinline__ uint32_t f2tf(float x) {
    uint32_t r; asm("cvt.rna.tf32.f32 %0, %1;" : "=r"(r) : "f"(x)); return r;
}

// ---------------------------------------------------------------------------
// Kernel 1: q/k projection (unchanged from R1)
// ---------------------------------------------------------------------------
__global__ __launch_bounds__(256) void qk_proj_kernel(
    const float* __restrict__ x,
    const float* __restrict__ wq, const float* __restrict__ bq,
    const float* __restrict__ wk, const float* __restrict__ bk)
{
    __shared__ float xt[64][64];
    __shared__ float wqs[16][64];
    __shared__ float wks[16][64];
    const int b = blockIdx.y, n0 = blockIdx.x * 64, tid = threadIdx.x;
    const int n = tid & 63, og = tid >> 6;
    float aq[4] = {0.f,0.f,0.f,0.f};
    float ak[4] = {0.f,0.f,0.f,0.f};

    for (int c0 = 0; c0 < DC; c0 += 64) {
        __syncthreads();
        {
            const int j4 = (tid & 15) * 4, rb = tid >> 4;
            #pragma unroll
            for (int i = 0; i < 4; ++i) {
                int r = rb + i * 16;
                *(float4*)&xt[r][j4] =
                    *(const float4*)(x + ((size_t)b*DC + c0 + r)*DN + n0 + j4);
            }
            *(float4*)&wqs[rb][j4] = *(const float4*)(wq + rb*DC + c0 + j4);
            *(float4*)&wks[rb][j4] = *(const float4*)(wk + rb*DC + c0 + j4);
        }
        __syncthreads();
        #pragma unroll 16
        for (int cc = 0; cc < 64; ++cc) {
            float xv = xt[cc][n];
            #pragma unroll
            for (int oo = 0; oo < 4; ++oo) {
                aq[oo] = fmaf(wqs[og*4+oo][cc], xv, aq[oo]);
                ak[oo] = fmaf(wks[og*4+oo][cc], xv, ak[oo]);
            }
        }
    }
    float4 q4, k4;
    q4.x = aq[0] + bq[og*4+0]; q4.y = aq[1] + bq[og*4+1];
    q4.z = aq[2] + bq[og*4+2]; q4.w = aq[3] + bq[og*4+3];
    k4.x = ak[0] + bk[og*4+0]; k4.y = ak[1] + bk[og*4+1];
    k4.z = ak[2] + bk[og*4+2]; k4.w = ak[3] + bk[og*4+3];
    const int base = (b*DN + n0 + n)*DD + og*4;
    *(float4*)&g_q[base] = q4;
    *(float4*)&g_k[base] = k4;
}

// ---------------------------------------------------------------------------
// Kernel 2: V projection GEMM (unchanged from R1), output [b][m][c]
// ---------------------------------------------------------------------------
__global__ __launch_bounds__(256) void v_proj_kernel(
    const float* __restrict__ x,
    const float* __restrict__ wv, const float* __restrict__ bv)
{
    __shared__ float xs[64][64];
    __shared__ float ws[64][68];
    const int b = blockIdx.z, c0 = blockIdx.y * 64, n0 = blockIdx.x * 64;
    const int tid = threadIdx.x;
    const int tn = tid & 15, tc = tid >> 4;
    float acc[4][4];
    #pragma unroll
    for (int i = 0; i < 4; ++i)
        #pragma unroll
        for (int j = 0; j < 4; ++j) acc[i][j] = 0.f;

    for (int k0 = 0; k0 < DC; k0 += 64) {
        __syncthreads();
        {
            const int j4 = (tid & 15) * 4, rb = tid >> 4;
            #pragma unroll
            for (int i = 0; i < 4; ++i) {
                int r = rb + i * 16;
                *(float4*)&xs[r][j4] =
                    *(const float4*)(x + ((size_t)b*DC + k0 + r)*DN + n0 + j4);
                float4 w = *(const float4*)(wv + (size_t)(c0 + r)*DC + k0 + j4);
                ws[j4+0][r] = w.x; ws[j4+1][r] = w.y;
                ws[j4+2][r] = w.z; ws[j4+3][r] = w.w;
            }
        }
        __syncthreads();
        #pragma unroll 8
        for (int kk = 0; kk < 64; ++kk) {
            float4 a = *(float4*)&xs[kk][tn*4];
            float4 w = *(float4*)&ws[kk][tc*4];
            acc[0][0]=fmaf(w.x,a.x,acc[0][0]); acc[0][1]=fmaf(w.x,a.y,acc[0][1]);
            acc[0][2]=fmaf(w.x,a.z,acc[0][2]); acc[0][3]=fmaf(w.x,a.w,acc[0][3]);
            acc[1][0]=fmaf(w.y,a.x,acc[1][0]); acc[1][1]=fmaf(w.y,a.y,acc[1][1]);
            acc[1][2]=fmaf(w.y,a.z,acc[1][2]); acc[1][3]=fmaf(w.y,a.w,acc[1][3]);
            acc[2][0]=fmaf(w.z,a.x,acc[2][0]); acc[2][1]=fmaf(w.z,a.y,acc[2][1]);
            acc[2][2]=fmaf(w.z,a.z,acc[2][2]); acc[2][3]=fmaf(w.z,a.w,acc[2][3]);
            acc[3][0]=fmaf(w.w,a.x,acc[3][0]); acc[3][1]=fmaf(w.w,a.y,acc[3][1]);
            acc[3][2]=fmaf(w.w,a.z,acc[3][2]); acc[3][3]=fmaf(w.w,a.w,acc[3][3]);
        }
    }
    float4 bvv = *(const float4*)(bv + c0 + tc*4);
    #pragma unroll
    for (int ni = 0; ni < 4; ++ni) {
        float4 o;
        o.x = acc[0][ni] + bvv.x; o.y = acc[1][ni] + bvv.y;
        o.z = acc[2][ni] + bvv.z; o.w = acc[3][ni] + bvv.w;
        *(float4*)&g_v[(b*DN + n0 + tn*4 + ni)*DC + c0 + tc*4] = o;
    }
}

// ---------------------------------------------------------------------------
// Kernel 3: flash attention with tf32 tensor-core mma + epilogue.
// Grid (N/64, B), 256 threads (8 warps).
// Warp w: row-tile rt = w&3 (16 rows), channel half chalf = w>>2 (128 ch).
// ---------------------------------------------------------------------------
__global__ __launch_bounds__(256, 2) void attn_kernel(
    const float* __restrict__ x, float* __restrict__ y,
    const float* __restrict__ gamma)
{
    extern __shared__ float sm[];
    float* qs = sm;                 // 64 x QSP(20)  = 1280
    float* ks = sm + 1280;          // 64 x KSP(20)  = 1280
    float* ps = sm + 2560;          // 64 x PSP(68)  = 4352
    float* vs = sm + 6912;          // 64 x VSP(264) = 16896  (end 23808)
    __shared__ float srm[64], srl[64], sfac[64];

    const int b = blockIdx.y, n0 = blockIdx.x * 64, tid = threadIdx.x;
    const int wid = tid >> 5, lane = tid & 31;
    const int g = lane >> 2, t = lane & 3;
    const int rt = wid & 3, chalf = wid >> 2;
    const int row0 = rt*16 + g, row1 = row0 + 8;

    float acc[16][4];
    #pragma unroll
    for (int i = 0; i < 16; ++i) {
        acc[i][0] = 0.f; acc[i][1] = 0.f; acc[i][2] = 0.f; acc[i][3] = 0.f;
    }

    // load q tile: row = tid>>2, 4 cols
    {
        int r = tid >> 2, c = (tid & 3) * 4;
        *(float4*)&qs[r*QSP + c] = *(const float4*)(g_q + ((size_t)b*DN + n0 + r)*DD + c);
    }
    if (tid < 64) { srm[tid] = -1e30f; srl[tid] = 0.f; }
    __syncthreads();

    // Q A-fragments (loop-invariant): 2 k-steps
    uint32_t aq[2][4];
    #pragma unroll
    for (int s = 0; s < 2; ++s) {
        aq[s][0] = f2tf(qs[row0*QSP + s*8 + t]);
        aq[s][1] = f2tf(qs[row1*QSP + s*8 + t]);
        aq[s][2] = f2tf(qs[row0*QSP + s*8 + t + 4]);
        aq[s][3] = f2tf(qs[row1*QSP + s*8 + t + 4]);
    }

    for (int m0 = 0; m0 < DN; m0 += 64) {
        __syncthreads();   // prev consumers done with ks/vs/ps
        // load K tile (64x16) and V tile (64x256)
        {
            int r = tid >> 2, c = (tid & 3) * 4;
            *(float4*)&ks[r*KSP + c] = *(const float4*)(g_k + ((size_t)b*DN + m0 + r)*DD + c);
            #pragma unroll
            for (int i = 0; i < 16; ++i) {
                int lin = i*256 + tid;
                int vr = lin >> 6, c4 = (lin & 63) * 4;
                *(float4*)&vs[vr*VSP + c4] =
                    *(const float4*)(g_v + ((size_t)b*DN + m0 + vr)*DC + c4);
            }
        }
        __syncthreads();

        // S = Q K^T: each warp 4 col-tiles (8 keys each)
        #pragma unroll
        for (int j = 0; j < 4; ++j) {
            int ct = chalf*4 + j;
            float d0 = 0.f, d1 = 0.f, d2 = 0.f, d3 = 0.f;
            #pragma unroll
            for (int s = 0; s < 2; ++s) {
                uint32_t b0 = __float_as_uint(ks[(ct*8 + g)*KSP + s*8 + t]);
                uint32_t b1 = __float_as_uint(ks[(ct*8 + g)*KSP + s*8 + t + 4]);
                mma_tf32(d0, d1, d2, d3, aq[s][0], aq[s][1], aq[s][2], aq[s][3], b0, b1);
            }
            *(float2*)&ps[row0*PSP + ct*8 + 2*t] = make_float2(d0, d1);
            *(float2*)&ps[row1*PSP + ct*8 + 2*t] = make_float2(d2, d3);
        }
        __syncthreads();

        // online softmax: 4 threads per row, 16 cols each
        {
            int r = tid >> 2, qd = tid & 3;
            float* pr = ps + r*PSP + qd*16;
            float tmax = pr[0];
            #pragma unroll
            for (int i = 1; i < 16; ++i) tmax = fmaxf(tmax, pr[i]);
            tmax = fmaxf(tmax, __shfl_xor_sync(0xffffffffu, tmax, 1));
            tmax = fmaxf(tmax, __shfl_xor_sync(0xffffffffu, tmax, 2));
            float om = srm[r];
            float nm = fmaxf(om, tmax);
            float s = 0.f;
            #pragma unroll
            for (int i = 0; i < 16; ++i) {
                float p = __expf(pr[i] - nm);
                pr[i] = p;
                s += p;
            }
            s += __shfl_xor_sync(0xffffffffu, s, 1);
            s += __shfl_xor_sync(0xffffffffu, s, 2);
            if (qd == 0) {
                float f = __expf(om - nm);
                srm[r]  = nm;
                srl[r]  = srl[r]*f + s;
                sfac[r] = f;
            }
        }
        __syncthreads();

        // rescale accumulators
        {
            float f0 = sfac[row0], f1 = sfac[row1];
            #pragma unroll
            for (int i = 0; i < 16; ++i) {
                acc[i][0] *= f0; acc[i][1] *= f0;
                acc[i][2] *= f1; acc[i][3] *= f1;
            }
        }

        // P*V: 8 k-steps of 8 keys
        #pragma unroll
        for (int k8 = 0; k8 < 8; ++k8) {
            uint32_t a0 = f2tf(ps[row0*PSP + k8*8 + t]);
            uint32_t a1 = f2tf(ps[row1*PSP + k8*8 + t]);
            uint32_t a2 = f2tf(ps[row0*PSP + k8*8 + t + 4]);
            uint32_t a3 = f2tf(ps[row1*PSP + k8*8 + t + 4]);
            const float* vrow0 = vs + (k8*8 + t)*VSP + chalf*128 + g;
            const float* vrow1 = vs + (k8*8 + t + 4)*VSP + chalf*128 + g;
            #pragma unroll
            for (int nt = 0; nt < 16; ++nt) {
                uint32_t b0 = __float_as_uint(vrow0[nt*8]);
                uint32_t b1 = __float_as_uint(vrow1[nt*8]);
                mma_tf32(acc[nt][0], acc[nt][1], acc[nt][2], acc[nt][3],
                         a0, a1, a2, a3, b0, b1);
            }
        }
    }
    __syncthreads();   // all done with vs/ps; smem reused for staging

    // stage normalized output [ch][n] then coalesced epilogue
    {
        float inv0 = 1.0f / srl[row0], inv1 = 1.0f / srl[row1];
        #pragma unroll
        for (int nt = 0; nt < 16; ++nt) {
            int ch = chalf*128 + nt*8 + 2*t;
            sm[ch*OSP + row0]     = acc[nt][0] * inv0;
            sm[(ch+1)*OSP + row0] = acc[nt][1] * inv0;
            sm[ch*OSP + row1]     = acc[nt][2] * inv1;
            sm[(ch+1)*OSP + row1] = acc[nt][3] * inv1;
        }
    }
    __syncthreads();
    {
        const float gm = gamma[0];
        const int j = (tid & 15) * 4, cb = tid >> 4;
        #pragma unroll
        for (int i = 0; i < 16; ++i) {
            int c = cb + i*16;
            float4 xv = *(const float4*)(x + ((size_t)b*DC + c)*DN + n0 + j);
            float4 ov = *(const float4*)&sm[c*OSP + j];
            float4 r;
            r.x = fmaf(gm, ov.x, xv.x); r.y = fmaf(gm, ov.y, xv.y);
            r.z = fmaf(gm, ov.z, xv.z); r.w = fmaf(gm, ov.w, xv.w);
            *(float4*)(y + ((size_t)b*DC + c)*DN + n0 + j) = r;
        }
    }
}

// ---------------------------------------------------------------------------
extern "C" void kernel_launch(void* const* d_in, const int* in_sizes, int n_in,
                              void* d_out, int out_size)
{
    const float* x     = (const float*)d_in[0];
    const float* wq    = (const float*)d_in[1];
    const float* bq    = (const float*)d_in[2];
    const float* wk    = (const float*)d_in[3];
    const float* bk    = (const float*)d_in[4];
    const float* wv    = (const float*)d_in[5];
    const float* bv    = (const float*)d_in[6];
    const float* gamma = (const float*)d_in[7];
    float* y = (float*)d_out;

    const int smem_bytes = 23808 * sizeof(float);   // 95232 B
    cudaFuncSetAttribute(attn_kernel,
                         cudaFuncAttributeMaxDynamicSharedMemorySize, smem_bytes);

    qk_proj_kernel<<<dim3(DN/64, DB), 256>>>(x, wq, bq, wk, bk);
    v_proj_kernel<<<dim3(DN/64, DC/64, DB), 256>>>(x, wv, bv);
    attn_kernel<<<dim3(DN/64, DB), 256, smem_bytes>>>(x, y, gamma);
}

// round 4
// speedup vs baseline: 5.8267x; 1.5735x over previous
#include <cuda_runtime.h>
#include <cuda_fp16.h>
#include <cstdint>

#define DB 4
#define DC 256
#define DN 4096
#define DD 16

#define QSH 24   // halves per q row
#define KSH 24   // halves per k row
#define SSP 68   // floats per score row
#define PHP 72   // halves per P row
#define VSH 72   // halves per V^T row (64 keys + 8 pad)
#define OSP 68   // floats per staging row

// Scratch (allocation-free rule: __device__ globals)
__device__ __half g_q[DB*DN*DD];   // [b][n][d]
__device__ __half g_k[DB*DN*DD];   // [b][m][d]
__device__ __half g_v[DB*DC*DN];   // [b][c][m]  (transposed!)

// ---------------------------------------------------------------------------
// fp16 mma m16n8k16 (fp32 accum)
// ---------------------------------------------------------------------------
__device__ __forceinline__ void mma_f16(float& d0, float& d1, float& d2, float& d3,
    uint32_t a0, uint32_t a1, uint32_t a2, uint32_t a3, uint32_t b0, uint32_t b1)
{
    asm volatile(
        "mma.sync.aligned.m16n8k16.row.col.f32.f16.f16.f32 "
        "{%0,%1,%2,%3}, {%4,%5,%6,%7}, {%8,%9}, {%0,%1,%2,%3};\n"
        : "+f"(d0), "+f"(d1), "+f"(d2), "+f"(d3)
        : "r"(a0), "r"(a1), "r"(a2), "r"(a3), "r"(b0), "r"(b1));
}

// ---------------------------------------------------------------------------
// Kernel 1: q/k projection -> fp16 [n][d]
// ---------------------------------------------------------------------------
__global__ __launch_bounds__(256) void qk_proj_kernel(
    const float* __restrict__ x,
    const float* __restrict__ wq, const float* __restrict__ bq,
    const float* __restrict__ wk, const float* __restrict__ bk)
{
    __shared__ float xt[64][64];
    __shared__ float wqs[16][64];
    __shared__ float wks[16][64];
    const int b = blockIdx.y, n0 = blockIdx.x * 64, tid = threadIdx.x;
    const int n = tid & 63, og = tid >> 6;
    float aq[4] = {0.f,0.f,0.f,0.f};
    float ak[4] = {0.f,0.f,0.f,0.f};

    for (int c0 = 0; c0 < DC; c0 += 64) {
        __syncthreads();
        {
            const int j4 = (tid & 15) * 4, rb = tid >> 4;
            #pragma unroll
            for (int i = 0; i < 4; ++i) {
                int r = rb + i * 16;
                *(float4*)&xt[r][j4] =
                    *(const float4*)(x + ((size_t)b*DC + c0 + r)*DN + n0 + j4);
            }
            *(float4*)&wqs[rb][j4] = *(const float4*)(wq + rb*DC + c0 + j4);
            *(float4*)&wks[rb][j4] = *(const float4*)(wk + rb*DC + c0 + j4);
        }
        __syncthreads();
        #pragma unroll 16
        for (int cc = 0; cc < 64; ++cc) {
            float xv = xt[cc][n];
            #pragma unroll
            for (int oo = 0; oo < 4; ++oo) {
                aq[oo] = fmaf(wqs[og*4+oo][cc], xv, aq[oo]);
                ak[oo] = fmaf(wks[og*4+oo][cc], xv, ak[oo]);
            }
        }
    }
    const int base = (b*DN + n0 + n)*DD + og*4;
    uint2 qh, kh;
    ((__half2*)&qh)[0] = __floats2half2_rn(aq[0]+bq[og*4+0], aq[1]+bq[og*4+1]);
    ((__half2*)&qh)[1] = __floats2half2_rn(aq[2]+bq[og*4+2], aq[3]+bq[og*4+3]);
    ((__half2*)&kh)[0] = __floats2half2_rn(ak[0]+bk[og*4+0], ak[1]+bk[og*4+1]);
    ((__half2*)&kh)[1] = __floats2half2_rn(ak[2]+bk[og*4+2], ak[3]+bk[og*4+3]);
    *(uint2*)&g_q[base] = qh;
    *(uint2*)&g_k[base] = kh;
}

// ---------------------------------------------------------------------------
// Kernel 2: V projection GEMM -> fp16 transposed [b][c][m]
// ---------------------------------------------------------------------------
__global__ __launch_bounds__(256) void v_proj_kernel(
    const float* __restrict__ x,
    const float* __restrict__ wv, const float* __restrict__ bv)
{
    __shared__ float xs[64][64];
    __shared__ float ws[64][68];
    const int b = blockIdx.z, c0 = blockIdx.y * 64, n0 = blockIdx.x * 64;
    const int tid = threadIdx.x;
    const int tn = tid & 15, tc = tid >> 4;
    float acc[4][4];
    #pragma unroll
    for (int i = 0; i < 4; ++i)
        #pragma unroll
        for (int j = 0; j < 4; ++j) acc[i][j] = 0.f;

    for (int k0 = 0; k0 < DC; k0 += 64) {
        __syncthreads();
        {
            const int j4 = (tid & 15) * 4, rb = tid >> 4;
            #pragma unroll
            for (int i = 0; i < 4; ++i) {
                int r = rb + i * 16;
                *(float4*)&xs[r][j4] =
                    *(const float4*)(x + ((size_t)b*DC + k0 + r)*DN + n0 + j4);
                float4 w = *(const float4*)(wv + (size_t)(c0 + r)*DC + k0 + j4);
                ws[j4+0][r] = w.x; ws[j4+1][r] = w.y;
                ws[j4+2][r] = w.z; ws[j4+3][r] = w.w;
            }
        }
        __syncthreads();
        #pragma unroll 8
        for (int kk = 0; kk < 64; ++kk) {
            float4 a = *(float4*)&xs[kk][tn*4];
            float4 w = *(float4*)&ws[kk][tc*4];
            acc[0][0]=fmaf(w.x,a.x,acc[0][0]); acc[0][1]=fmaf(w.x,a.y,acc[0][1]);
            acc[0][2]=fmaf(w.x,a.z,acc[0][2]); acc[0][3]=fmaf(w.x,a.w,acc[0][3]);
            acc[1][0]=fmaf(w.y,a.x,acc[1][0]); acc[1][1]=fmaf(w.y,a.y,acc[1][1]);
            acc[1][2]=fmaf(w.y,a.z,acc[1][2]); acc[1][3]=fmaf(w.y,a.w,acc[1][3]);
            acc[2][0]=fmaf(w.z,a.x,acc[2][0]); acc[2][1]=fmaf(w.z,a.y,acc[2][1]);
            acc[2][2]=fmaf(w.z,a.z,acc[2][2]); acc[2][3]=fmaf(w.z,a.w,acc[2][3]);
            acc[3][0]=fmaf(w.w,a.x,acc[3][0]); acc[3][1]=fmaf(w.w,a.y,acc[3][1]);
            acc[3][2]=fmaf(w.w,a.z,acc[3][2]); acc[3][3]=fmaf(w.w,a.w,acc[3][3]);
        }
    }
    float4 bvv = *(const float4*)(bv + c0 + tc*4);
    const float bvc[4] = {bvv.x, bvv.y, bvv.z, bvv.w};
    #pragma unroll
    for (int i = 0; i < 4; ++i) {
        uint2 h;
        ((__half2*)&h)[0] = __floats2half2_rn(acc[i][0]+bvc[i], acc[i][1]+bvc[i]);
        ((__half2*)&h)[1] = __floats2half2_rn(acc[i][2]+bvc[i], acc[i][3]+bvc[i]);
        *(uint2*)&g_v[((size_t)b*DC + c0 + tc*4 + i)*DN + n0 + tn*4] = h;
    }
}

// ---------------------------------------------------------------------------
// Kernel 3: flash attention, fp16 mma m16n8k16, V^T smem layout.
// Grid (N/64, B), 256 threads (8 warps).
// S-phase:   warp = rowtile (wid&3, 16 rows) x 8 keys x (wid>>2)*4+j coltiles
// PV-phase:  warp = rows (wid&1)*32..+31, channels (wid>>1)*64..+63
// ---------------------------------------------------------------------------
__global__ __launch_bounds__(256, 2) void attn_kernel(
    const float* __restrict__ x, float* __restrict__ y,
    const float* __restrict__ gamma)
{
    extern __shared__ float sm[];
    __half* qs = (__half*)sm;                 // 64 x 24 halves = 768 f
    __half* ks = (__half*)(sm + 768);         // 64 x 24 halves = 768 f
    float*  ss = sm + 1536;                   // 64 x 68 floats = 4352 f
    __half* ph = (__half*)(sm + 5888);        // 64 x 72 halves = 2304 f
    __half* vs = (__half*)(sm + 8192);        // 256 x 72 halves = 9216 f (end 17408)
    __shared__ float srm[64], srl[64], sfac[64];

    const int b = blockIdx.y, n0 = blockIdx.x * 64, tid = threadIdx.x;
    const int wid = tid >> 5, lane = tid & 31;
    const int g = lane >> 2, t = lane & 3;
    // S-phase mapping
    const int row0s = (wid & 3)*16 + g, row1s = row0s + 8;
    // PV-phase mapping
    const int rp = wid & 1, chq = wid >> 1;
    const int rb0 = rp*32 + g;                 // rows rb0, rb0+8, rb0+16, rb0+24

    float acc[2][8][4];
    #pragma unroll
    for (int m = 0; m < 2; ++m)
        #pragma unroll
        for (int n = 0; n < 8; ++n) {
            acc[m][n][0]=0.f; acc[m][n][1]=0.f; acc[m][n][2]=0.f; acc[m][n][3]=0.f;
        }

    // load q tile (fp16)
    {
        int r = tid >> 2, c = (tid & 3) * 4;
        *(uint2*)&qs[r*QSH + c] = *(const uint2*)&g_q[((size_t)b*DN + n0 + r)*DD + c];
    }
    if (tid < 64) { srm[tid] = -1e30f; srl[tid] = 0.f; }
    __syncthreads();

    // Q A-fragments (loop-invariant)
    uint32_t aq0 = *(uint32_t*)&qs[row0s*QSH + 2*t];
    uint32_t aq1 = *(uint32_t*)&qs[row1s*QSH + 2*t];
    uint32_t aq2 = *(uint32_t*)&qs[row0s*QSH + 8 + 2*t];
    uint32_t aq3 = *(uint32_t*)&qs[row1s*QSH + 8 + 2*t];

    for (int m0 = 0; m0 < DN; m0 += 64) {
        __syncthreads();   // prev consumers done with ks/vs/ph
        // K tile (64 x 16 halves)
        {
            int r = tid >> 2, c = (tid & 3) * 4;
            *(uint2*)&ks[r*KSH + c] = *(const uint2*)&g_k[((size_t)b*DN + m0 + r)*DD + c];
        }
        // V^T tile (256 ch x 64 keys, fp16): thread (ch=tid>>3 (+32i), j=tid&7)
        {
            const int j8 = (tid & 7) * 8, chb = tid >> 3;
            #pragma unroll
            for (int i = 0; i < 8; ++i) {
                int ch = chb + i*32;
                *(uint4*)&vs[ch*VSH + j8] =
                    *(const uint4*)&g_v[((size_t)b*DC + ch)*DN + m0 + j8];
            }
        }
        __syncthreads();

        // S = Q K^T: warp does 4 n8 col-tiles
        #pragma unroll
        for (int j = 0; j < 4; ++j) {
            int ct = (wid >> 2)*4 + j;
            uint32_t b0 = *(uint32_t*)&ks[(ct*8 + g)*KSH + 2*t];
            uint32_t b1 = *(uint32_t*)&ks[(ct*8 + g)*KSH + 8 + 2*t];
            float d0=0.f, d1=0.f, d2=0.f, d3=0.f;
            mma_f16(d0, d1, d2, d3, aq0, aq1, aq2, aq3, b0, b1);
            *(float2*)&ss[row0s*SSP + ct*8 + 2*t] = make_float2(d0, d1);
            *(float2*)&ss[row1s*SSP + ct*8 + 2*t] = make_float2(d2, d3);
        }
        __syncthreads();

        // online softmax: 4 threads/row, write P as fp16
        {
            int r = tid >> 2, qd = tid & 3;
            float* pr = ss + r*SSP + qd*16;
            __half* pw = ph + r*PHP + qd*16;
            float tmax = pr[0];
            #pragma unroll
            for (int i = 1; i < 16; ++i) tmax = fmaxf(tmax, pr[i]);
            tmax = fmaxf(tmax, __shfl_xor_sync(0xffffffffu, tmax, 1));
            tmax = fmaxf(tmax, __shfl_xor_sync(0xffffffffu, tmax, 2));
            float om = srm[r];
            float nm = fmaxf(om, tmax);
            float s = 0.f;
            #pragma unroll
            for (int i = 0; i < 16; i += 2) {
                float p0 = __expf(pr[i]   - nm);
                float p1 = __expf(pr[i+1] - nm);
                s += p0 + p1;
                *(__half2*)&pw[i] = __floats2half2_rn(p0, p1);
            }
            s += __shfl_xor_sync(0xffffffffu, s, 1);
            s += __shfl_xor_sync(0xffffffffu, s, 2);
            if (qd == 0) {
                float f = __expf(om - nm);
                srm[r]  = nm;
                srl[r]  = srl[r]*f + s;
                sfac[r] = f;
            }
        }
        __syncthreads();

        // rescale accumulators
        {
            float f00 = sfac[rb0],    f01 = sfac[rb0+8];
            float f10 = sfac[rb0+16], f11 = sfac[rb0+24];
            #pragma unroll
            for (int n = 0; n < 8; ++n) {
                acc[0][n][0]*=f00; acc[0][n][1]*=f00; acc[0][n][2]*=f01; acc[0][n][3]*=f01;
                acc[1][n][0]*=f10; acc[1][n][1]*=f10; acc[1][n][2]*=f11; acc[1][n][3]*=f11;
            }
        }

        // P*V: 4 k16 steps; B-fragments shared across the 2 M-tiles
        #pragma unroll
        for (int k16 = 0; k16 < 4; ++k16) {
            const int ko = k16*16;
            uint32_t a00 = *(uint32_t*)&ph[(rb0   )*PHP + ko + 2*t];
            uint32_t a01 = *(uint32_t*)&ph[(rb0+ 8)*PHP + ko + 2*t];
            uint32_t a02 = *(uint32_t*)&ph[(rb0   )*PHP + ko + 8 + 2*t];
            uint32_t a03 = *(uint32_t*)&ph[(rb0+ 8)*PHP + ko + 8 + 2*t];
            uint32_t a10 = *(uint32_t*)&ph[(rb0+16)*PHP + ko + 2*t];
            uint32_t a11 = *(uint32_t*)&ph[(rb0+24)*PHP + ko + 2*t];
            uint32_t a12 = *(uint32_t*)&ph[(rb0+16)*PHP + ko + 8 + 2*t];
            uint32_t a13 = *(uint32_t*)&ph[(rb0+24)*PHP + ko + 8 + 2*t];
            #pragma unroll
            for (int nt = 0; nt < 8; ++nt) {
                const int ch = chq*64 + nt*8 + g;
                uint32_t b0 = *(uint32_t*)&vs[ch*VSH + ko + 2*t];
                uint32_t b1 = *(uint32_t*)&vs[ch*VSH + ko + 8 + 2*t];
                mma_f16(acc[0][nt][0], acc[0][nt][1], acc[0][nt][2], acc[0][nt][3],
                        a00, a01, a02, a03, b0, b1);
                mma_f16(acc[1][nt][0], acc[1][nt][1], acc[1][nt][2], acc[1][nt][3],
                        a10, a11, a12, a13, b0, b1);
            }
        }
    }
    __syncthreads();   // done with vs/ph; reuse all smem for staging

    // stage normalized output [ch][n] (256 x 68 floats = exactly the smem)
    {
        float inv00 = 1.0f/srl[rb0],    inv01 = 1.0f/srl[rb0+8];
        float inv10 = 1.0f/srl[rb0+16], inv11 = 1.0f/srl[rb0+24];
        #pragma unroll
        for (int nt = 0; nt < 8; ++nt) {
            int ch = chq*64 + nt*8 + 2*t;
            sm[ ch   *OSP + rb0   ] = acc[0][nt][0]*inv00;
            sm[(ch+1)*OSP + rb0   ] = acc[0][nt][1]*inv00;
            sm[ ch   *OSP + rb0+8 ] = acc[0][nt][2]*inv01;
            sm[(ch+1)*OSP + rb0+8 ] = acc[0][nt][3]*inv01;
            sm[ ch   *OSP + rb0+16] = acc[1][nt][0]*inv10;
            sm[(ch+1)*OSP + rb0+16] = acc[1][nt][1]*inv10;
            sm[ ch   *OSP + rb0+24] = acc[1][nt][2]*inv11;
            sm[(ch+1)*OSP + rb0+24] = acc[1][nt][3]*inv11;
        }
    }
    __syncthreads();
    {
        const float gm = gamma[0];
        const int j = (tid & 15) * 4, cb = tid >> 4;
        #pragma unroll
        for (int i = 0; i < 16; ++i) {
            int c = cb + i*16;
            float4 xv = *(const float4*)(x + ((size_t)b*DC + c)*DN + n0 + j);
            float4 ov = *(const float4*)&sm[c*OSP + j];
            float4 r;
            r.x = fmaf(gm, ov.x, xv.x); r.y = fmaf(gm, ov.y, xv.y);
            r.z = fmaf(gm, ov.z, xv.z); r.w = fmaf(gm, ov.w, xv.w);
            *(float4*)(y + ((size_t)b*DC + c)*DN + n0 + j) = r;
        }
    }
}

// ---------------------------------------------------------------------------
extern "C" void kernel_launch(void* const* d_in, const int* in_sizes, int n_in,
                              void* d_out, int out_size)
{
    const float* x     = (const float*)d_in[0];
    const float* wq    = (const float*)d_in[1];
    const float* bq    = (const float*)d_in[2];
    const float* wk    = (const float*)d_in[3];
    const float* bk    = (const float*)d_in[4];
    const float* wv    = (const float*)d_in[5];
    const float* bv    = (const float*)d_in[6];
    const float* gamma = (const float*)d_in[7];
    float* y = (float*)d_out;

    const int smem_bytes = 17408 * sizeof(float);   // 69632 B
    cudaFuncSetAttribute(attn_kernel,
                         cudaFuncAttributeMaxDynamicSharedMemorySize, smem_bytes);

    qk_proj_kernel<<<dim3(DN/64, DB), 256>>>(x, wq, bq, wk, bk);
    v_proj_kernel<<<dim3(DN/64, DC/64, DB), 256>>>(x, wv, bv);
    attn_kernel<<<dim3(DN/64, DB), 256, smem_bytes>>>(x, y, gamma);
}